// round 10
// baseline (speedup 1.0000x reference)
#include <cuda_runtime.h>

// PoseLSTM v9: v8 math sliced into 4 barrier domains per SM, anti-phased.
//   512 blocks x 200 threads, __launch_bounds__(200,4) -> 4 blocks/SM on
//   128 SMs, single wave. thread = (l,u,gp): 2 gate rows (i,f | g,o) for
//   2 batch elements. Startup stagger (blockIdx&3)*~400cyc anti-phases the
//   four co-resident blocks so their barriers interleave.
//   20x fma.rn.f32x2 per element, bias folded into first FMA2;
//   pair exchange: shfl.xor(1); 1 syncthreads/step, parity unrolled.

#define T_ 1024
#define B_ 1024
#define L_ 10
#define H_ 10
#define NB 2
#define NTH 200

typedef unsigned long long u64;

__device__ __forceinline__ u64 pk2(float lo, float hi) {
    u64 r; asm("mov.b64 %0, {%1,%2};" : "=l"(r) : "f"(lo), "f"(hi)); return r;
}
__device__ __forceinline__ void upk2(u64 v, float& lo, float& hi) {
    asm("mov.b64 {%0,%1}, %2;" : "=f"(lo), "=f"(hi) : "l"(v));
}
__device__ __forceinline__ u64 fma2(u64 a, u64 b, u64 c) {
    u64 d; asm("fma.rn.f32x2 %0, %1, %2, %3;" : "=l"(d) : "l"(a), "l"(b), "l"(c));
    return d;
}
__device__ __forceinline__ u64 mul2(u64 a, u64 b) {
    u64 d; asm("mul.rn.f32x2 %0, %1, %2;" : "=l"(d) : "l"(a), "l"(b));
    return d;
}
__device__ __forceinline__ u64 add2(u64 a, u64 b) {
    u64 d; asm("add.rn.f32x2 %0, %1, %2;" : "=l"(d) : "l"(a), "l"(b));
    return d;
}
__device__ __forceinline__ float tanhap(float x) {
    float r; asm("tanh.approx.f32 %0, %1;" : "=f"(r) : "f"(x)); return r;
}

// matvec for one element: 2 gate rows, 4 chains, bias pre-folded
__device__ __forceinline__ void matvec2(const ulonglong2* zz,
                                        const u64* wA, const u64* wB,
                                        u64 biasA2, u64 biasB2,
                                        float& pA, float& pB) {
    ulonglong2 v0 = zz[0], v1 = zz[1], v2 = zz[2], v3 = zz[3], v4 = zz[4];
    u64 a  = fma2(wA[0], v0.x, biasA2);
    u64 a_ = mul2(wA[1], v0.y);
    u64 b  = fma2(wB[0], v0.x, biasB2);
    u64 b_ = mul2(wB[1], v0.y);
    a  = fma2(wA[2], v1.x, a);  a_ = fma2(wA[3], v1.y, a_);
    b  = fma2(wB[2], v1.x, b);  b_ = fma2(wB[3], v1.y, b_);
    a  = fma2(wA[4], v2.x, a);  a_ = fma2(wA[5], v2.y, a_);
    b  = fma2(wB[4], v2.x, b);  b_ = fma2(wB[5], v2.y, b_);
    a  = fma2(wA[6], v3.x, a);  a_ = fma2(wA[7], v3.y, a_);
    b  = fma2(wB[6], v3.x, b);  b_ = fma2(wB[7], v3.y, b_);
    a  = fma2(wA[8], v4.x, a);  a_ = fma2(wA[9], v4.y, a_);
    b  = fma2(wB[8], v4.x, b);  b_ = fma2(wB[9], v4.y, b_);
    u64 sA = add2(a, a_), sB = add2(b, b_);
    float lo, hi;
    upk2(sA, lo, hi); pA = lo + hi;
    upk2(sB, lo, hi); pB = lo + hi;
}

__global__ __launch_bounds__(NTH, 4)
void lstm_pipe9(const float* __restrict__ x,   // (T,B,H)
                const float* __restrict__ hp,  // (L,B,H)
                const float* __restrict__ cp,  // (L,B,H)
                const float* __restrict__ Wih, // (L,4H,H)
                const float* __restrict__ Whh, // (L,4H,H)
                const float* __restrict__ bih, // (L,4H)
                const float* __restrict__ bhh, // (L,4H)
                float* __restrict__ out)       // ys ++ hn ++ cn
{
    // z[buf][layer][elem(2)][24]: 0..9 input-from-below, 10..19 own h.
    __shared__ __align__(16) float z[2][L_ + 1][NB][24];   // 4224 B

    // anti-phase the 4 co-resident blocks (~400 cyc apart)
    {
        unsigned ph = blockIdx.x & 3;
        if (ph) {
            long long t0 = clock64();
            while ((long long)(clock64() - t0) < (long long)(ph * 400)) {}
        }
    }

    const int tid = threadIdx.x;
    const int l   = tid / 20;
    const int r   = tid % 20;          // u*2 + gp
    const int u   = r >> 1;
    const int gp  = r & 1;             // 0: (i,f)   1: (g~,o)
    const int b   = blockIdx.x * NB;   // element 0
    const int b2  = b + 1;             // element 1
    const unsigned mask = (tid < 192) ? 0xFFFFFFFFu : 0x000000FFu;

    // ---- k-packed register-stationary weights, sigmoid 0.5 folded ----
    const int rowA = l * 40 + gp * 20 + u;    // i (gp0) or g~ (gp1)
    const int rowB = rowA + 10;               // f (gp0) or o  (gp1)
    const float sclA = gp ? 1.0f : 0.5f;
    u64 wA[10], wB[10];
    {
        const float* WiA = Wih + rowA * 10; const float* WhA = Whh + rowA * 10;
        const float* WiB = Wih + rowB * 10; const float* WhB = Whh + rowB * 10;
#pragma unroll
        for (int k = 0; k < 5; ++k) {
            wA[k]     = pk2(sclA * __ldg(WiA + 2 * k), sclA * __ldg(WiA + 2 * k + 1));
            wA[5 + k] = pk2(sclA * __ldg(WhA + 2 * k), sclA * __ldg(WhA + 2 * k + 1));
            wB[k]     = pk2(0.5f * __ldg(WiB + 2 * k), 0.5f * __ldg(WiB + 2 * k + 1));
            wB[5 + k] = pk2(0.5f * __ldg(WhB + 2 * k), 0.5f * __ldg(WhB + 2 * k + 1));
        }
    }
    const u64 biasA2 = pk2(sclA * (bih[rowA] + bhh[rowA]), 0.0f);
    const u64 biasB2 = pk2(0.5f * (bih[rowB] + bhh[rowB]), 0.0f);
    const float cAa = gp ? 0.0f : 0.5f;   // act A: gp0 sigmoid, gp1 tanh
    const float cBa = gp ? 1.0f : 0.5f;

    // ---- init state ----
    float c  = cp[(l * B_ + b ) * H_ + u];
    float c2 = cp[(l * B_ + b2) * H_ + u];
    if (gp == 0) {
        z[l & 1][l][0][10 + u] = hp[(l * B_ + b ) * H_ + u];
        z[l & 1][l][1][10 + u] = hp[(l * B_ + b2) * H_ + u];
    }
    const bool isLdr = (l == 0 && gp == 0);
    if (isLdr) {
        z[0][0][0][u] = x[(size_t)b  * H_ + u];
        z[0][0][1][u] = x[(size_t)b2 * H_ + u];
    }

    const size_t base_hn = (size_t)T_ * B_ * H_;
    const size_t base_cn = base_hn + (size_t)L_ * B_ * H_;

    // ---- wavefront main loop, parity-unrolled ----
    for (int s0 = 0; s0 < 1034; s0 += 2) {
#pragma unroll
        for (int par = 0; par < 2; ++par) {
            const int scur = s0 + par;
            const int t = scur - l;
            const bool act = ((unsigned)t < (unsigned)T_);

            float xl, xl2;
            const bool ldrGo = isLdr && (scur + 1 < T_);
            if (ldrGo) {
                xl  = x[((size_t)(scur + 1) * B_ + b ) * H_ + u];
                xl2 = x[((size_t)(scur + 1) * B_ + b2) * H_ + u];
            }

            __syncthreads();   // step s-1 z-writes -> step s z-reads

            const ulonglong2* zzA =
                reinterpret_cast<const ulonglong2*>(&z[par][l][0][0]);
            const ulonglong2* zzB =
                reinterpret_cast<const ulonglong2*>(&z[par][l][1][0]);

            float pA, pB, qA, qB;
            matvec2(zzA, wA, wB, biasA2, biasB2, pA, pB);
            matvec2(zzB, wA, wB, biasA2, biasB2, qA, qB);

            // ---- activations ----
            float vA  = fmaf(cBa,  tanhap(pA), cAa);
            float vB  = fmaf(0.5f, tanhap(pB), 0.5f);
            float vA2 = fmaf(cBa,  tanhap(qA), cAa);
            float vB2 = fmaf(0.5f, tanhap(qB), 0.5f);

            // ---- pair exchange + cell update ----
            float Ao  = __shfl_xor_sync(mask, vA, 1);
            float Bo  = __shfl_xor_sync(mask, vB, 1);
            float Ao2 = __shfl_xor_sync(mask, vA2, 1);
            float Bo2 = __shfl_xor_sync(mask, vB2, 1);
            float F  = gp ? Bo  : vB;
            float O  = gp ? vB  : Bo;
            float F2 = gp ? Bo2 : vB2;
            float O2 = gp ? vB2 : Bo2;
            if (act) {
                c  = fmaf(F,  c,  vA  * Ao);
                c2 = fmaf(F2, c2, vA2 * Ao2);
            }
            float h  = O  * tanhap(c);
            float h2 = O2 * tanhap(c2);

            // ---- h handoff / outputs ----
            if (act) {
                if (gp == 0) {
                    z[par ^ 1][l][0][10 + u] = h;
                    z[par ^ 1][l][1][10 + u] = h2;
                } else if (l < L_ - 1) {
                    z[par ^ 1][l + 1][0][u] = h;
                    z[par ^ 1][l + 1][1][u] = h2;
                } else {
                    out[((size_t)t * B_ + b ) * H_ + u] = h;
                    out[((size_t)t * B_ + b2) * H_ + u] = h2;
                }
                if (t == T_ - 1) {
                    if (gp == 0) {
                        out[base_hn + ((size_t)l * B_ + b ) * H_ + u] = h;
                        out[base_hn + ((size_t)l * B_ + b2) * H_ + u] = h2;
                    } else {
                        out[base_cn + ((size_t)l * B_ + b ) * H_ + u] = c;
                        out[base_cn + ((size_t)l * B_ + b2) * H_ + u] = c2;
                    }
                }
            }
            if (ldrGo) {
                z[par ^ 1][0][0][u] = xl;
                z[par ^ 1][0][1][u] = xl2;
            }
        }
    }
}

extern "C" void kernel_launch(void* const* d_in, const int* in_sizes, int n_in,
                              void* d_out, int out_size) {
    const float* x   = (const float*)d_in[0];
    const float* hp  = (const float*)d_in[1];
    const float* cp  = (const float*)d_in[2];
    const float* Wih = (const float*)d_in[3];
    const float* Whh = (const float*)d_in[4];
    const float* bih = (const float*)d_in[5];
    const float* bhh = (const float*)d_in[6];
    float* out = (float*)d_out;

    dim3 grid(B_ / NB);   // 512 blocks; 4 blocks/SM -> single wave on 128 SMs
    dim3 block(NTH);      // 200 threads
    lstm_pipe9<<<grid, block>>>(x, hp, cp, Wih, Whh, bih, bhh, out);
}

// round 11
// speedup vs baseline: 1.0716x; 1.0716x over previous
#include <cuda_runtime.h>

// PoseLSTM v10: v8 (best: 909us) + steady-phase straight-lining.
//   256 blocks x 400 threads, 2 blocks/SM, single wave, 2 barrier domains/SM.
//   thread = (l, u, eh, gp): 2 gate rows (i,f | g,o) for elements eh, eh+2.
//   Loop split: ramp-up s=0..9 (generic) / steady s=10..1021 (no act guards,
//   no tail checks, compile-time parity) / ramp-down s=1022..1033 (generic).

#define T_ 1024
#define B_ 1024
#define L_ 10
#define H_ 10
#define NB 4
#define NTH 400

typedef unsigned long long u64;

template <bool B> struct BoolC { static constexpr bool value = B; };

__device__ __forceinline__ u64 pk2(float lo, float hi) {
    u64 r; asm("mov.b64 %0, {%1,%2};" : "=l"(r) : "f"(lo), "f"(hi)); return r;
}
__device__ __forceinline__ void upk2(u64 v, float& lo, float& hi) {
    asm("mov.b64 {%0,%1}, %2;" : "=f"(lo), "=f"(hi) : "l"(v));
}
__device__ __forceinline__ u64 fma2(u64 a, u64 b, u64 c) {
    u64 d; asm("fma.rn.f32x2 %0, %1, %2, %3;" : "=l"(d) : "l"(a), "l"(b), "l"(c));
    return d;
}
__device__ __forceinline__ u64 mul2(u64 a, u64 b) {
    u64 d; asm("mul.rn.f32x2 %0, %1, %2;" : "=l"(d) : "l"(a), "l"(b));
    return d;
}
__device__ __forceinline__ u64 add2(u64 a, u64 b) {
    u64 d; asm("add.rn.f32x2 %0, %1, %2;" : "=l"(d) : "l"(a), "l"(b));
    return d;
}
__device__ __forceinline__ float tanhap(float x) {
    float r; asm("tanh.approx.f32 %0, %1;" : "=f"(r) : "f"(x)); return r;
}

// matvec for one element: 2 gate rows, 4 chains, bias pre-folded
__device__ __forceinline__ void matvec2(const ulonglong2* zz,
                                        const u64* wA, const u64* wB,
                                        u64 biasA2, u64 biasB2,
                                        float& pA, float& pB) {
    ulonglong2 v0 = zz[0], v1 = zz[1], v2 = zz[2], v3 = zz[3], v4 = zz[4];
    u64 a  = fma2(wA[0], v0.x, biasA2);
    u64 a_ = mul2(wA[1], v0.y);
    u64 b  = fma2(wB[0], v0.x, biasB2);
    u64 b_ = mul2(wB[1], v0.y);
    a  = fma2(wA[2], v1.x, a);  a_ = fma2(wA[3], v1.y, a_);
    b  = fma2(wB[2], v1.x, b);  b_ = fma2(wB[3], v1.y, b_);
    a  = fma2(wA[4], v2.x, a);  a_ = fma2(wA[5], v2.y, a_);
    b  = fma2(wB[4], v2.x, b);  b_ = fma2(wB[5], v2.y, b_);
    a  = fma2(wA[6], v3.x, a);  a_ = fma2(wA[7], v3.y, a_);
    b  = fma2(wB[6], v3.x, b);  b_ = fma2(wB[7], v3.y, b_);
    a  = fma2(wA[8], v4.x, a);  a_ = fma2(wA[9], v4.y, a_);
    b  = fma2(wB[8], v4.x, b);  b_ = fma2(wB[9], v4.y, b_);
    u64 sA = add2(a, a_), sB = add2(b, b_);
    float lo, hi;
    upk2(sA, lo, hi); pA = lo + hi;
    upk2(sB, lo, hi); pB = lo + hi;
}

__global__ __launch_bounds__(NTH, 2)
void lstm_pipe10(const float* __restrict__ x,   // (T,B,H)
                 const float* __restrict__ hp,  // (L,B,H)
                 const float* __restrict__ cp,  // (L,B,H)
                 const float* __restrict__ Wih, // (L,4H,H)
                 const float* __restrict__ Whh, // (L,4H,H)
                 const float* __restrict__ bih, // (L,4H)
                 const float* __restrict__ bhh, // (L,4H)
                 float* __restrict__ out)       // ys ++ hn ++ cn
{
    // z[buf][layer][elem(4)][24]: 0..9 input-from-below, 10..19 own h.
    __shared__ __align__(16) float z[2][L_ + 1][NB][24];

    const int tid = threadIdx.x;
    const int l   = tid / 40;
    const int r   = tid % 40;          // u*4 + eh*2 + gp
    const int u   = r >> 2;
    const int eh  = (r >> 1) & 1;      // element slots eh and eh+2
    const int gp  = r & 1;             // 0: (i,f)   1: (g~,o)
    const int e2  = eh + 2;
    const int b   = blockIdx.x * NB + eh;
    const int b2  = b + 2;

    // ---- k-packed register-stationary weights, sigmoid 0.5 folded ----
    const int rowA = l * 40 + gp * 20 + u;    // i (gp0) or g~ (gp1)
    const int rowB = rowA + 10;               // f (gp0) or o  (gp1)
    const float sclA = gp ? 1.0f : 0.5f;
    u64 wA[10], wB[10];
    {
        const float* WiA = Wih + rowA * 10; const float* WhA = Whh + rowA * 10;
        const float* WiB = Wih + rowB * 10; const float* WhB = Whh + rowB * 10;
#pragma unroll
        for (int k = 0; k < 5; ++k) {
            wA[k]     = pk2(sclA * __ldg(WiA + 2 * k), sclA * __ldg(WiA + 2 * k + 1));
            wA[5 + k] = pk2(sclA * __ldg(WhA + 2 * k), sclA * __ldg(WhA + 2 * k + 1));
            wB[k]     = pk2(0.5f * __ldg(WiB + 2 * k), 0.5f * __ldg(WiB + 2 * k + 1));
            wB[5 + k] = pk2(0.5f * __ldg(WhB + 2 * k), 0.5f * __ldg(WhB + 2 * k + 1));
        }
    }
    const u64 biasA2 = pk2(sclA * (bih[rowA] + bhh[rowA]), 0.0f);
    const u64 biasB2 = pk2(0.5f * (bih[rowB] + bhh[rowB]), 0.0f);
    const float cAa = gp ? 0.0f : 0.5f;   // act A: gp0 sigmoid, gp1 tanh
    const float cBa = gp ? 1.0f : 0.5f;

    // ---- init state ----
    float c  = cp[(l * B_ + b ) * H_ + u];
    float c2 = cp[(l * B_ + b2) * H_ + u];
    if (gp == 0) {
        z[l & 1][l][eh][10 + u] = hp[(l * B_ + b ) * H_ + u];
        z[l & 1][l][e2][10 + u] = hp[(l * B_ + b2) * H_ + u];
    }
    const bool isLdr = (l == 0 && gp == 0);
    if (isLdr) {
        z[0][0][eh][u] = x[(size_t)b  * H_ + u];
        z[0][0][e2][u] = x[(size_t)b2 * H_ + u];
    }

    const size_t base_hn = (size_t)T_ * B_ * H_;
    const size_t base_cn = base_hn + (size_t)L_ * B_ * H_;

    // ---- one wavefront step (ST = steady: no guards, no tail checks) ----
    auto stepf = [&](int scur, int par, auto SC) {
        constexpr bool ST = decltype(SC)::value;
        const int t = scur - l;
        const bool act = ST ? true : ((unsigned)t < (unsigned)T_);

        float xl, xl2;
        const bool ldrGo = isLdr && (ST ? true : (scur + 1 < T_));
        if (ldrGo) {
            xl  = x[((size_t)(scur + 1) * B_ + b ) * H_ + u];
            xl2 = x[((size_t)(scur + 1) * B_ + b2) * H_ + u];
        }

        __syncthreads();   // step s-1 z-writes -> step s z-reads

        const ulonglong2* zzA =
            reinterpret_cast<const ulonglong2*>(&z[par][l][eh][0]);
        const ulonglong2* zzB =
            reinterpret_cast<const ulonglong2*>(&z[par][l][e2][0]);

        float pA, pB, qA, qB;
        matvec2(zzA, wA, wB, biasA2, biasB2, pA, pB);
        matvec2(zzB, wA, wB, biasA2, biasB2, qA, qB);

        float vA  = fmaf(cBa,  tanhap(pA), cAa);
        float vB  = fmaf(0.5f, tanhap(pB), 0.5f);
        float vA2 = fmaf(cBa,  tanhap(qA), cAa);
        float vB2 = fmaf(0.5f, tanhap(qB), 0.5f);

        float Ao  = __shfl_xor_sync(0xFFFFFFFFu, vA, 1);
        float Bo  = __shfl_xor_sync(0xFFFFFFFFu, vB, 1);
        float Ao2 = __shfl_xor_sync(0xFFFFFFFFu, vA2, 1);
        float Bo2 = __shfl_xor_sync(0xFFFFFFFFu, vB2, 1);
        float F  = gp ? Bo  : vB;
        float O  = gp ? vB  : Bo;
        float F2 = gp ? Bo2 : vB2;
        float O2 = gp ? vB2 : Bo2;
        if (act) {
            c  = fmaf(F,  c,  vA  * Ao);
            c2 = fmaf(F2, c2, vA2 * Ao2);
        }
        float h  = O  * tanhap(c);
        float h2 = O2 * tanhap(c2);

        if (act) {
            if (gp == 0) {
                z[par ^ 1][l][eh][10 + u] = h;
                z[par ^ 1][l][e2][10 + u] = h2;
            } else if (l < L_ - 1) {
                z[par ^ 1][l + 1][eh][u] = h;
                z[par ^ 1][l + 1][e2][u] = h2;
            } else {
                out[((size_t)t * B_ + b ) * H_ + u] = h;
                out[((size_t)t * B_ + b2) * H_ + u] = h2;
            }
            if (!ST && t == T_ - 1) {
                if (gp == 0) {
                    out[base_hn + ((size_t)l * B_ + b ) * H_ + u] = h;
                    out[base_hn + ((size_t)l * B_ + b2) * H_ + u] = h2;
                } else {
                    out[base_cn + ((size_t)l * B_ + b ) * H_ + u] = c;
                    out[base_cn + ((size_t)l * B_ + b2) * H_ + u] = c2;
                }
            }
        }
        if (ldrGo) {
            z[par ^ 1][0][eh][u] = xl;
            z[par ^ 1][0][e2][u] = xl2;
        }
    };

    // ---- ramp-up: s = 0..9 (layers activate; generic) ----
    for (int s = 0; s < L_; ++s)
        stepf(s, s & 1, BoolC<false>{});

    // ---- steady: s = 10..1021, all layers active, no tail events ----
    for (int s0 = L_; s0 < T_ - 2; s0 += 2) {
        stepf(s0,     0, BoolC<true>{});
        stepf(s0 + 1, 1, BoolC<true>{});
    }

    // ---- ramp-down: s = 1022..1033 (t==T-1 events; generic) ----
    for (int s = T_ - 2; s < T_ + L_; ++s)
        stepf(s, s & 1, BoolC<false>{});
}

extern "C" void kernel_launch(void* const* d_in, const int* in_sizes, int n_in,
                              void* d_out, int out_size) {
    const float* x   = (const float*)d_in[0];
    const float* hp  = (const float*)d_in[1];
    const float* cp  = (const float*)d_in[2];
    const float* Wih = (const float*)d_in[3];
    const float* Whh = (const float*)d_in[4];
    const float* bih = (const float*)d_in[5];
    const float* bhh = (const float*)d_in[6];
    float* out = (float*)d_out;

    dim3 grid(B_ / NB);   // 256 blocks; 2 blocks/SM -> single wave on 128 SMs
    dim3 block(NTH);      // 400 threads
    lstm_pipe10<<<grid, block>>>(x, hp, cp, Wih, Whh, bih, bhh, out);
}

// round 12
// speedup vs baseline: 1.2822x; 1.1965x over previous
#include <cuda_runtime.h>

// PoseLSTM v11: v10 + cell specialization (lane owns one element post-matvec).
//   256 blocks x 400 threads, 2 blocks/SM, single wave, 2 barrier domains/SM.
//   thread = (l, u, eh, gp): computes 2 gate rows (i,f | g,o) for elements
//   eh and eh+2, then finishes the CELL of only ITS element (gp0->eh, gp1->e2):
//   2 shfl.xor(1) exchange the cross gates; no redundant cell math.
//   Loop: ramp-up / steady (straight-line) / ramp-down.

#define T_ 1024
#define B_ 1024
#define L_ 10
#define H_ 10
#define NB 4
#define NTH 400

typedef unsigned long long u64;

template <bool B> struct BoolC { static constexpr bool value = B; };

__device__ __forceinline__ u64 pk2(float lo, float hi) {
    u64 r; asm("mov.b64 %0, {%1,%2};" : "=l"(r) : "f"(lo), "f"(hi)); return r;
}
__device__ __forceinline__ void upk2(u64 v, float& lo, float& hi) {
    asm("mov.b64 {%0,%1}, %2;" : "=f"(lo), "=f"(hi) : "l"(v));
}
__device__ __forceinline__ u64 fma2(u64 a, u64 b, u64 c) {
    u64 d; asm("fma.rn.f32x2 %0, %1, %2, %3;" : "=l"(d) : "l"(a), "l"(b), "l"(c));
    return d;
}
__device__ __forceinline__ u64 mul2(u64 a, u64 b) {
    u64 d; asm("mul.rn.f32x2 %0, %1, %2;" : "=l"(d) : "l"(a), "l"(b));
    return d;
}
__device__ __forceinline__ u64 add2(u64 a, u64 b) {
    u64 d; asm("add.rn.f32x2 %0, %1, %2;" : "=l"(d) : "l"(a), "l"(b));
    return d;
}
__device__ __forceinline__ float tanhap(float x) {
    float r; asm("tanh.approx.f32 %0, %1;" : "=f"(r) : "f"(x)); return r;
}

// matvec for one element: 2 gate rows, 4 chains, bias pre-folded
__device__ __forceinline__ void matvec2(const ulonglong2* zz,
                                        const u64* wA, const u64* wB,
                                        u64 biasA2, u64 biasB2,
                                        float& pA, float& pB) {
    ulonglong2 v0 = zz[0], v1 = zz[1], v2 = zz[2], v3 = zz[3], v4 = zz[4];
    u64 a  = fma2(wA[0], v0.x, biasA2);
    u64 a_ = mul2(wA[1], v0.y);
    u64 b  = fma2(wB[0], v0.x, biasB2);
    u64 b_ = mul2(wB[1], v0.y);
    a  = fma2(wA[2], v1.x, a);  a_ = fma2(wA[3], v1.y, a_);
    b  = fma2(wB[2], v1.x, b);  b_ = fma2(wB[3], v1.y, b_);
    a  = fma2(wA[4], v2.x, a);  a_ = fma2(wA[5], v2.y, a_);
    b  = fma2(wB[4], v2.x, b);  b_ = fma2(wB[5], v2.y, b_);
    a  = fma2(wA[6], v3.x, a);  a_ = fma2(wA[7], v3.y, a_);
    b  = fma2(wB[6], v3.x, b);  b_ = fma2(wB[7], v3.y, b_);
    a  = fma2(wA[8], v4.x, a);  a_ = fma2(wA[9], v4.y, a_);
    b  = fma2(wB[8], v4.x, b);  b_ = fma2(wB[9], v4.y, b_);
    u64 sA = add2(a, a_), sB = add2(b, b_);
    float lo, hi;
    upk2(sA, lo, hi); pA = lo + hi;
    upk2(sB, lo, hi); pB = lo + hi;
}

__global__ __launch_bounds__(NTH, 2)
void lstm_pipe11(const float* __restrict__ x,   // (T,B,H)
                 const float* __restrict__ hp,  // (L,B,H)
                 const float* __restrict__ cp,  // (L,B,H)
                 const float* __restrict__ Wih, // (L,4H,H)
                 const float* __restrict__ Whh, // (L,4H,H)
                 const float* __restrict__ bih, // (L,4H)
                 const float* __restrict__ bhh, // (L,4H)
                 float* __restrict__ out)       // ys ++ hn ++ cn
{
    // z[buf][layer][elem(4)][24]: 0..9 input-from-below, 10..19 own h.
    __shared__ __align__(16) float z[2][L_ + 1][NB][24];

    const int tid = threadIdx.x;
    const int l   = tid / 40;
    const int r   = tid % 40;          // u*4 + eh*2 + gp
    const int u   = r >> 2;
    const int eh  = (r >> 1) & 1;      // element slots eh and eh+2
    const int gp  = r & 1;             // 0: rows (i,f)  1: rows (g~,o)
    const int e2  = eh + 2;
    const int em  = gp ? e2 : eh;      // the element THIS lane finishes
    const int bm  = blockIdx.x * NB + em;
    const int b1  = blockIdx.x * NB + eh;   // gate-element 1
    const int b2  = b1 + 2;                 // gate-element 2

    // ---- k-packed register-stationary weights, sigmoid 0.5 folded ----
    const int rowA = l * 40 + gp * 20 + u;    // i (gp0) or g~ (gp1)
    const int rowB = rowA + 10;               // f (gp0) or o  (gp1)
    const float sclA = gp ? 1.0f : 0.5f;
    u64 wA[10], wB[10];
    {
        const float* WiA = Wih + rowA * 10; const float* WhA = Whh + rowA * 10;
        const float* WiB = Wih + rowB * 10; const float* WhB = Whh + rowB * 10;
#pragma unroll
        for (int k = 0; k < 5; ++k) {
            wA[k]     = pk2(sclA * __ldg(WiA + 2 * k), sclA * __ldg(WiA + 2 * k + 1));
            wA[5 + k] = pk2(sclA * __ldg(WhA + 2 * k), sclA * __ldg(WhA + 2 * k + 1));
            wB[k]     = pk2(0.5f * __ldg(WiB + 2 * k), 0.5f * __ldg(WiB + 2 * k + 1));
            wB[5 + k] = pk2(0.5f * __ldg(WhB + 2 * k), 0.5f * __ldg(WhB + 2 * k + 1));
        }
    }
    const u64 biasA2 = pk2(sclA * (bih[rowA] + bhh[rowA]), 0.0f);
    const u64 biasB2 = pk2(0.5f * (bih[rowB] + bhh[rowB]), 0.0f);
    const float cAa = gp ? 0.0f : 0.5f;   // act A: gp0 sigmoid, gp1 tanh
    const float cBa = gp ? 1.0f : 0.5f;

    // ---- init state (one element per lane) ----
    float cm = cp[(l * B_ + bm) * H_ + u];
    z[l & 1][l][em][10 + u] = hp[(l * B_ + bm) * H_ + u];
    const bool isLdr = (l == 0);
    if (isLdr)
        z[0][0][em][u] = x[(size_t)bm * H_ + u];

    const size_t base_hn = (size_t)T_ * B_ * H_;
    const size_t base_cn = base_hn + (size_t)L_ * B_ * H_;

    // ---- one wavefront step (ST = steady: no guards, no tail checks) ----
    auto stepf = [&](int scur, int par, auto SC) {
        constexpr bool ST = decltype(SC)::value;
        const int t = scur - l;
        const bool act = ST ? true : ((unsigned)t < (unsigned)T_);

        float xl;
        const bool ldrGo = isLdr && (ST ? true : (scur + 1 < T_));
        if (ldrGo)
            xl = x[((size_t)(scur + 1) * B_ + bm) * H_ + u];

        __syncthreads();   // step s-1 z-writes -> step s z-reads

        const ulonglong2* zzA =
            reinterpret_cast<const ulonglong2*>(&z[par][l][eh][0]);
        const ulonglong2* zzB =
            reinterpret_cast<const ulonglong2*>(&z[par][l][e2][0]);

        float pA, pB, qA, qB;
        matvec2(zzA, wA, wB, biasA2, biasB2, pA, pB);   // gates for elem eh
        matvec2(zzB, wA, wB, biasA2, biasB2, qA, qB);   // gates for elem e2

        float vA  = fmaf(cBa,  tanhap(pA), cAa);   // eh gateA (i | g~)
        float vB  = fmaf(0.5f, tanhap(pB), 0.5f);  // eh gateB (f | o)
        float vA2 = fmaf(cBa,  tanhap(qA), cAa);   // e2 gateA
        float vB2 = fmaf(0.5f, tanhap(qB), 0.5f);  // e2 gateB

        // exchange: each lane keeps ITS element's gates, ships the other's
        float ownA = gp ? vA2 : vA;    // gp0: i(eh)  gp1: g(e2)
        float ownB = gp ? vB2 : vB;    // gp0: f(eh)  gp1: o(e2)
        float sndA = gp ? vA  : vA2;   // value belonging to partner's element
        float sndB = gp ? vB  : vB2;
        float rcvA = __shfl_xor_sync(0xFFFFFFFFu, sndA, 1); // gp0: g(eh) gp1: i(e2)
        float rcvB = __shfl_xor_sync(0xFFFFFFFFu, sndB, 1); // gp0: o(eh) gp1: f(e2)
        float F = gp ? rcvB : ownB;
        float O = gp ? ownB : rcvB;
        if (act) cm = fmaf(F, cm, ownA * rcvA);    // i*g~ symmetric
        float hm = O * tanhap(cm);

        if (act) {
            z[par ^ 1][l][em][10 + u] = hm;        // own-h for next step
            if (l < L_ - 1) {
                z[par ^ 1][l + 1][em][u] = hm;     // input for layer above
            } else {
                out[((size_t)t * B_ + bm) * H_ + u] = hm;
            }
            if (!ST && t == T_ - 1) {
                out[base_hn + ((size_t)l * B_ + bm) * H_ + u] = hm;
                out[base_cn + ((size_t)l * B_ + bm) * H_ + u] = cm;
            }
        }
        if (ldrGo)
            z[par ^ 1][0][em][u] = xl;
    };

    // ---- ramp-up: s = 0..9 ----
    for (int s = 0; s < L_; ++s)
        stepf(s, s & 1, BoolC<false>{});

    // ---- steady: s = 10..1021 ----
    for (int s0 = L_; s0 < T_ - 2; s0 += 2) {
        stepf(s0,     0, BoolC<true>{});
        stepf(s0 + 1, 1, BoolC<true>{});
    }

    // ---- ramp-down: s = 1022..1033 ----
    for (int s = T_ - 2; s < T_ + L_; ++s)
        stepf(s, s & 1, BoolC<false>{});
}

extern "C" void kernel_launch(void* const* d_in, const int* in_sizes, int n_in,
                              void* d_out, int out_size) {
    const float* x   = (const float*)d_in[0];
    const float* hp  = (const float*)d_in[1];
    const float* cp  = (const float*)d_in[2];
    const float* Wih = (const float*)d_in[3];
    const float* Whh = (const float*)d_in[4];
    const float* bih = (const float*)d_in[5];
    const float* bhh = (const float*)d_in[6];
    float* out = (float*)d_out;

    dim3 grid(B_ / NB);   // 256 blocks; 2 blocks/SM -> single wave on 128 SMs
    dim3 block(NTH);      // 400 threads
    lstm_pipe11<<<grid, block>>>(x, hp, cp, Wih, Whh, bih, bhh, out);
}

// round 13
// speedup vs baseline: 1.3040x; 1.0170x over previous
#include <cuda_runtime.h>

// PoseLSTM v12: v11 (best: 754us) + anti-phase stagger + steady unroll x4.
//   256 blocks x 400 threads, 2 blocks/SM (108 SMs paired, pairs = (bid, bid+148)).
//   Blocks bid>=148 spin ~750cyc at entry so co-resident blocks run anti-phased:
//   one block's post-barrier dependency chain overlaps the other's issue burst.
//   thread = (l, u, eh, gp): 2 gate rows (i,f | g,o) for elements eh, eh+2,
//   then finishes the CELL of only ITS element; 2 shfl.xor(1) exchange.

#define T_ 1024
#define B_ 1024
#define L_ 10
#define H_ 10
#define NB 4
#define NTH 400

typedef unsigned long long u64;

template <bool B> struct BoolC { static constexpr bool value = B; };

__device__ __forceinline__ u64 pk2(float lo, float hi) {
    u64 r; asm("mov.b64 %0, {%1,%2};" : "=l"(r) : "f"(lo), "f"(hi)); return r;
}
__device__ __forceinline__ void upk2(u64 v, float& lo, float& hi) {
    asm("mov.b64 {%0,%1}, %2;" : "=f"(lo), "=f"(hi) : "l"(v));
}
__device__ __forceinline__ u64 fma2(u64 a, u64 b, u64 c) {
    u64 d; asm("fma.rn.f32x2 %0, %1, %2, %3;" : "=l"(d) : "l"(a), "l"(b), "l"(c));
    return d;
}
__device__ __forceinline__ u64 mul2(u64 a, u64 b) {
    u64 d; asm("mul.rn.f32x2 %0, %1, %2;" : "=l"(d) : "l"(a), "l"(b));
    return d;
}
__device__ __forceinline__ u64 add2(u64 a, u64 b) {
    u64 d; asm("add.rn.f32x2 %0, %1, %2;" : "=l"(d) : "l"(a), "l"(b));
    return d;
}
__device__ __forceinline__ float tanhap(float x) {
    float r; asm("tanh.approx.f32 %0, %1;" : "=f"(r) : "f"(x)); return r;
}

// matvec for one element: 2 gate rows, 4 chains, bias pre-folded
__device__ __forceinline__ void matvec2(const ulonglong2* zz,
                                        const u64* wA, const u64* wB,
                                        u64 biasA2, u64 biasB2,
                                        float& pA, float& pB) {
    ulonglong2 v0 = zz[0], v1 = zz[1], v2 = zz[2], v3 = zz[3], v4 = zz[4];
    u64 a  = fma2(wA[0], v0.x, biasA2);
    u64 a_ = mul2(wA[1], v0.y);
    u64 b  = fma2(wB[0], v0.x, biasB2);
    u64 b_ = mul2(wB[1], v0.y);
    a  = fma2(wA[2], v1.x, a);  a_ = fma2(wA[3], v1.y, a_);
    b  = fma2(wB[2], v1.x, b);  b_ = fma2(wB[3], v1.y, b_);
    a  = fma2(wA[4], v2.x, a);  a_ = fma2(wA[5], v2.y, a_);
    b  = fma2(wB[4], v2.x, b);  b_ = fma2(wB[5], v2.y, b_);
    a  = fma2(wA[6], v3.x, a);  a_ = fma2(wA[7], v3.y, a_);
    b  = fma2(wB[6], v3.x, b);  b_ = fma2(wB[7], v3.y, b_);
    a  = fma2(wA[8], v4.x, a);  a_ = fma2(wA[9], v4.y, a_);
    b  = fma2(wB[8], v4.x, b);  b_ = fma2(wB[9], v4.y, b_);
    u64 sA = add2(a, a_), sB = add2(b, b_);
    float lo, hi;
    upk2(sA, lo, hi); pA = lo + hi;
    upk2(sB, lo, hi); pB = lo + hi;
}

__global__ __launch_bounds__(NTH, 2)
void lstm_pipe12(const float* __restrict__ x,   // (T,B,H)
                 const float* __restrict__ hp,  // (L,B,H)
                 const float* __restrict__ cp,  // (L,B,H)
                 const float* __restrict__ Wih, // (L,4H,H)
                 const float* __restrict__ Whh, // (L,4H,H)
                 const float* __restrict__ bih, // (L,4H)
                 const float* __restrict__ bhh, // (L,4H)
                 float* __restrict__ out)       // ys ++ hn ++ cn
{
    // z[buf][layer][elem(4)][24]: 0..9 input-from-below, 10..19 own h.
    __shared__ __align__(16) float z[2][L_ + 1][NB][24];

    // anti-phase: second CTA on each SM (wave-1 deterministic: bid>=148)
    if (blockIdx.x >= 148) {
        long long t0 = clock64();
        while ((long long)(clock64() - t0) < 750LL) {}
    }

    const int tid = threadIdx.x;
    const int l   = tid / 40;
    const int r   = tid % 40;          // u*4 + eh*2 + gp
    const int u   = r >> 2;
    const int eh  = (r >> 1) & 1;      // element slots eh and eh+2
    const int gp  = r & 1;             // 0: rows (i,f)  1: rows (g~,o)
    const int e2  = eh + 2;
    const int em  = gp ? e2 : eh;      // the element THIS lane finishes
    const int bm  = blockIdx.x * NB + em;

    // ---- k-packed register-stationary weights, sigmoid 0.5 folded ----
    const int rowA = l * 40 + gp * 20 + u;    // i (gp0) or g~ (gp1)
    const int rowB = rowA + 10;               // f (gp0) or o  (gp1)
    const float sclA = gp ? 1.0f : 0.5f;
    u64 wA[10], wB[10];
    {
        const float* WiA = Wih + rowA * 10; const float* WhA = Whh + rowA * 10;
        const float* WiB = Wih + rowB * 10; const float* WhB = Whh + rowB * 10;
#pragma unroll
        for (int k = 0; k < 5; ++k) {
            wA[k]     = pk2(sclA * __ldg(WiA + 2 * k), sclA * __ldg(WiA + 2 * k + 1));
            wA[5 + k] = pk2(sclA * __ldg(WhA + 2 * k), sclA * __ldg(WhA + 2 * k + 1));
            wB[k]     = pk2(0.5f * __ldg(WiB + 2 * k), 0.5f * __ldg(WiB + 2 * k + 1));
            wB[5 + k] = pk2(0.5f * __ldg(WhB + 2 * k), 0.5f * __ldg(WhB + 2 * k + 1));
        }
    }
    const u64 biasA2 = pk2(sclA * (bih[rowA] + bhh[rowA]), 0.0f);
    const u64 biasB2 = pk2(0.5f * (bih[rowB] + bhh[rowB]), 0.0f);
    const float cAa = gp ? 0.0f : 0.5f;   // act A: gp0 sigmoid, gp1 tanh
    const float cBa = gp ? 1.0f : 0.5f;

    // ---- init state (one element per lane) ----
    float cm = cp[(l * B_ + bm) * H_ + u];
    z[l & 1][l][em][10 + u] = hp[(l * B_ + bm) * H_ + u];
    const bool isLdr = (l == 0);
    if (isLdr)
        z[0][0][em][u] = x[(size_t)bm * H_ + u];

    const size_t base_hn = (size_t)T_ * B_ * H_;
    const size_t base_cn = base_hn + (size_t)L_ * B_ * H_;

    // ---- one wavefront step (ST = steady: no guards, no tail checks) ----
    auto stepf = [&](int scur, int par, auto SC) {
        constexpr bool ST = decltype(SC)::value;
        const int t = scur - l;
        const bool act = ST ? true : ((unsigned)t < (unsigned)T_);

        float xl;
        const bool ldrGo = isLdr && (ST ? true : (scur + 1 < T_));
        if (ldrGo)
            xl = x[((size_t)(scur + 1) * B_ + bm) * H_ + u];

        __syncthreads();   // step s-1 z-writes -> step s z-reads

        const ulonglong2* zzA =
            reinterpret_cast<const ulonglong2*>(&z[par][l][eh][0]);
        const ulonglong2* zzB =
            reinterpret_cast<const ulonglong2*>(&z[par][l][e2][0]);

        float pA, pB, qA, qB;
        matvec2(zzA, wA, wB, biasA2, biasB2, pA, pB);   // gates for elem eh
        matvec2(zzB, wA, wB, biasA2, biasB2, qA, qB);   // gates for elem e2

        float vA  = fmaf(cBa,  tanhap(pA), cAa);   // eh gateA (i | g~)
        float vB  = fmaf(0.5f, tanhap(pB), 0.5f);  // eh gateB (f | o)
        float vA2 = fmaf(cBa,  tanhap(qA), cAa);   // e2 gateA
        float vB2 = fmaf(0.5f, tanhap(qB), 0.5f);  // e2 gateB

        // each lane keeps ITS element's gates, ships the other's
        float ownA = gp ? vA2 : vA;
        float ownB = gp ? vB2 : vB;
        float sndA = gp ? vA  : vA2;
        float sndB = gp ? vB  : vB2;
        float rcvA = __shfl_xor_sync(0xFFFFFFFFu, sndA, 1);
        float rcvB = __shfl_xor_sync(0xFFFFFFFFu, sndB, 1);
        float F = gp ? rcvB : ownB;
        float O = gp ? ownB : rcvB;
        if (act) cm = fmaf(F, cm, ownA * rcvA);
        float hm = O * tanhap(cm);

        if (act) {
            z[par ^ 1][l][em][10 + u] = hm;
            if (l < L_ - 1) {
                z[par ^ 1][l + 1][em][u] = hm;
            } else {
                out[((size_t)t * B_ + bm) * H_ + u] = hm;
            }
            if (!ST && t == T_ - 1) {
                out[base_hn + ((size_t)l * B_ + bm) * H_ + u] = hm;
                out[base_cn + ((size_t)l * B_ + bm) * H_ + u] = cm;
            }
        }
        if (ldrGo)
            z[par ^ 1][0][em][u] = xl;
    };

    // ---- ramp-up: s = 0..9 ----
    for (int s = 0; s < L_; ++s)
        stepf(s, s & 1, BoolC<false>{});

    // ---- steady: s = 10..1021, unrolled x4 (1012 = 4*253) ----
    for (int s0 = L_; s0 < T_ - 2; s0 += 4) {
        stepf(s0,     0, BoolC<true>{});
        stepf(s0 + 1, 1, BoolC<true>{});
        stepf(s0 + 2, 0, BoolC<true>{});
        stepf(s0 + 3, 1, BoolC<true>{});
    }

    // ---- ramp-down: s = 1022..1033 ----
    for (int s = T_ - 2; s < T_ + L_; ++s)
        stepf(s, s & 1, BoolC<false>{});
}

extern "C" void kernel_launch(void* const* d_in, const int* in_sizes, int n_in,
                              void* d_out, int out_size) {
    const float* x   = (const float*)d_in[0];
    const float* hp  = (const float*)d_in[1];
    const float* cp  = (const float*)d_in[2];
    const float* Wih = (const float*)d_in[3];
    const float* Whh = (const float*)d_in[4];
    const float* bih = (const float*)d_in[5];
    const float* bhh = (const float*)d_in[6];
    float* out = (float*)d_out;

    dim3 grid(B_ / NB);   // 256 blocks
    dim3 block(NTH);      // 400 threads
    lstm_pipe12<<<grid, block>>>(x, hp, cp, Wih, Whh, bih, bhh, out);
}